// round 1
// baseline (speedup 1.0000x reference)
#include <cuda_runtime.h>
#include <cstdint>

#define N_NODES 100000
#define N_EDGES 3200000
#define F_IN    256
#define F_H     64   // = 16 float4

// ---------------- scratch (device globals: allocation-free) ----------------
__device__ __align__(16) float g_H  [(size_t)N_NODES * F_H];
__device__ __align__(16) float g_ACC[(size_t)N_NODES * F_H];
__device__ float g_dinv[N_NODES];
__device__ int   g_cnt [N_NODES];
__device__ int   g_is64;

// ---------------- edge-index dtype sniffer ----------------
// ids are in [0, 100000) so if data is int64 every odd int32 word is 0.
__global__ void detect_kernel(const int* __restrict__ ei32) {
    if (blockIdx.x == 0 && threadIdx.x == 0) {
        int ok64 = 1;
        #pragma unroll
        for (int i = 0; i < 8; ++i)
            if (ei32[2 * i + 1] != 0) ok64 = 0;
        g_is64 = ok64;
    }
}

__device__ __forceinline__ int load_idx(const void* ei, size_t pos, int is64) {
    if (is64) return (int)((const long long*)ei)[pos];
    return ((const int*)ei)[pos];
}

// ---------------- zero degree counters ----------------
__global__ void zero_cnt_kernel() {
    int n = blockIdx.x * blockDim.x + threadIdx.x;
    if (n < N_NODES) g_cnt[n] = 0;
}

// ---------------- degree count (dst side) ----------------
__global__ void count_kernel(const void* __restrict__ ei) {
    int e = blockIdx.x * blockDim.x + threadIdx.x;
    if (e >= N_EDGES) return;
    const int is64 = g_is64;
    int d = load_idx(ei, (size_t)N_EDGES + e, is64);
    atomicAdd(&g_cnt[d], 1);
}

// ---------------- dinv = rsqrt(deg + 1)  (self loop adds 1) ----------------
__global__ void dinv_kernel() {
    int n = blockIdx.x * blockDim.x + threadIdx.x;
    if (n < N_NODES) g_dinv[n] = rsqrtf((float)g_cnt[n] + 1.0f);
}

// ---------------- GEMM: H = x @ W_gcn  (100000x256 @ 256x64) ----------------
// Tile: 256 nodes x 64 cols per block, K-tile 16, 8x8 per thread (256 thr).
#define G_TN  256
#define G_KK  16
#define G_LDN 260   // padded row (floats); 260*4 bytes keeps 16B alignment

__global__ __launch_bounds__(256) void gemm_kernel(
    const float* __restrict__ x, const float* __restrict__ W)
{
    __shared__ float xs[G_KK * G_LDN];   // xs[k][n]  (transposed tile)
    __shared__ float ws[G_KK * 64];      // ws[k][c]

    const int tid = threadIdx.x;
    const int nodeBase = blockIdx.x * G_TN;
    const int tc = tid & 7;    // col group (8 groups * 8 cols)
    const int tn = tid >> 3;   // node group (32 groups * 8 nodes)
    const int lk = tid & 15;   // staging k
    const int lnb = tid >> 4;  // staging node base

    float acc[8][8];
    #pragma unroll
    for (int i = 0; i < 8; ++i)
        #pragma unroll
        for (int j = 0; j < 8; ++j) acc[i][j] = 0.0f;

    for (int kk = 0; kk < F_IN; kk += G_KK) {
        // stage x tile transposed
        #pragma unroll
        for (int p = 0; p < G_TN / 16; ++p) {
            int n = lnb + p * 16;
            int node = nodeBase + n;
            float v = 0.0f;
            if (node < N_NODES) v = x[(size_t)node * F_IN + kk + lk];
            xs[lk * G_LDN + n] = v;
        }
        // stage W tile (16*64 = 1024 elems, 4 per thread)
        #pragma unroll
        for (int p = 0; p < 4; ++p) {
            int idx = tid + p * 256;
            int k = idx >> 6, c = idx & 63;
            ws[idx] = W[(size_t)(kk + k) * 64 + c];
        }
        __syncthreads();

        #pragma unroll
        for (int k = 0; k < G_KK; ++k) {
            float4 a0 = *(const float4*)&xs[k * G_LDN + tn * 8];
            float4 a1 = *(const float4*)&xs[k * G_LDN + tn * 8 + 4];
            float4 b0 = *(const float4*)&ws[k * 64 + tc * 8];
            float4 b1 = *(const float4*)&ws[k * 64 + tc * 8 + 4];
            float av[8] = {a0.x, a0.y, a0.z, a0.w, a1.x, a1.y, a1.z, a1.w};
            float bv[8] = {b0.x, b0.y, b0.z, b0.w, b1.x, b1.y, b1.z, b1.w};
            #pragma unroll
            for (int i = 0; i < 8; ++i)
                #pragma unroll
                for (int j = 0; j < 8; ++j)
                    acc[i][j] += av[i] * bv[j];
        }
        __syncthreads();
    }

    #pragma unroll
    for (int i = 0; i < 8; ++i) {
        int node = nodeBase + tn * 8 + i;
        if (node < N_NODES) {
            float4 o0 = make_float4(acc[i][0], acc[i][1], acc[i][2], acc[i][3]);
            float4 o1 = make_float4(acc[i][4], acc[i][5], acc[i][6], acc[i][7]);
            *(float4*)&g_H[(size_t)node * F_H + tc * 8]     = o0;
            *(float4*)&g_H[(size_t)node * F_H + tc * 8 + 4] = o1;
        }
    }
}

// ---------------- self-loop init: ACC[i] = H[i] * dinv[i]^2 ----------------
__global__ void init_acc_kernel() {
    int idx = blockIdx.x * blockDim.x + threadIdx.x;  // over N_NODES*16 float4
    if (idx >= N_NODES * 16) return;
    int n = idx >> 4;
    float s = g_dinv[n];
    s = s * s;
    const float4* H4 = (const float4*)g_H;
    float4* A4 = (float4*)g_ACC;
    float4 v = H4[idx];
    A4[idx] = make_float4(v.x * s, v.y * s, v.z * s, v.w * s);
}

// ---------------- edge scatter: ACC[dst] += H[src] * norm ----------------
// 16 threads per edge; vectorized red.global.add.v4.f32 (sm_90+)
__global__ __launch_bounds__(256) void scatter_kernel(const void* __restrict__ ei) {
    long long idx = (long long)blockIdx.x * blockDim.x + threadIdx.x;
    if (idx >= (long long)N_EDGES * 16) return;
    const int is64 = g_is64;
    int e = (int)(idx >> 4);
    int c = (int)(idx & 15);
    int s = load_idx(ei, (size_t)e, is64);
    int d = load_idx(ei, (size_t)N_EDGES + e, is64);
    float nm = g_dinv[s] * g_dinv[d];

    const float4* H4 = (const float4*)g_H;
    float4 v = H4[(size_t)s * 16 + c];
    float4* dst = (float4*)g_ACC + (size_t)d * 16 + c;
    asm volatile("red.global.add.v4.f32 [%0], {%1,%2,%3,%4};"
                 :: "l"(dst), "f"(v.x * nm), "f"(v.y * nm),
                    "f"(v.z * nm), "f"(v.w * nm)
                 : "memory");
}

// ---------------- fused ReLU + MLP 64->32->16->10 ----------------
__global__ __launch_bounds__(128) void mlp_kernel(
    const float* __restrict__ b_gcn,
    const float* __restrict__ W1, const float* __restrict__ b1,
    const float* __restrict__ W2, const float* __restrict__ b2,
    const float* __restrict__ W3, const float* __restrict__ b3,
    float* __restrict__ out)
{
    __shared__ float sW1[64 * 32];
    __shared__ float sW2[32 * 16];
    __shared__ float sW3[16 * 10];
    __shared__ float sbg[64], sb1[32], sb2[16], sb3[10];

    const int tid = threadIdx.x;
    for (int i = tid; i < 64 * 32; i += 128) sW1[i] = W1[i];
    for (int i = tid; i < 32 * 16; i += 128) sW2[i] = W2[i];
    for (int i = tid; i < 16 * 10; i += 128) sW3[i] = W3[i];
    if (tid < 64) sbg[tid] = b_gcn[tid];
    if (tid < 32) sb1[tid] = b1[tid];
    if (tid < 16) sb2[tid] = b2[tid];
    if (tid < 10) sb3[tid] = b3[tid];
    __syncthreads();

    int node = blockIdx.x * 128 + tid;
    if (node >= N_NODES) return;

    // in = relu(ACC[node] + b_gcn)
    float in[64];
    const float4* A4 = (const float4*)g_ACC;
    #pragma unroll
    for (int q = 0; q < 16; ++q) {
        float4 v = A4[(size_t)node * 16 + q];
        in[4 * q + 0] = fmaxf(v.x + sbg[4 * q + 0], 0.0f);
        in[4 * q + 1] = fmaxf(v.y + sbg[4 * q + 1], 0.0f);
        in[4 * q + 2] = fmaxf(v.z + sbg[4 * q + 2], 0.0f);
        in[4 * q + 3] = fmaxf(v.w + sbg[4 * q + 3], 0.0f);
    }

    // h1 = relu(in @ W1 + b1)
    float h1[32];
    #pragma unroll
    for (int j = 0; j < 32; ++j) h1[j] = sb1[j];
    #pragma unroll
    for (int k = 0; k < 64; ++k) {
        float a = in[k];
        #pragma unroll
        for (int j = 0; j < 32; ++j) h1[j] += a * sW1[k * 32 + j];
    }
    #pragma unroll
    for (int j = 0; j < 32; ++j) h1[j] = fmaxf(h1[j], 0.0f);

    // h2 = relu(h1 @ W2 + b2)
    float h2[16];
    #pragma unroll
    for (int j = 0; j < 16; ++j) h2[j] = sb2[j];
    #pragma unroll
    for (int k = 0; k < 32; ++k) {
        float a = h1[k];
        #pragma unroll
        for (int j = 0; j < 16; ++j) h2[j] += a * sW2[k * 16 + j];
    }
    #pragma unroll
    for (int j = 0; j < 16; ++j) h2[j] = fmaxf(h2[j], 0.0f);

    // o = h2 @ W3 + b3
    float o[10];
    #pragma unroll
    for (int j = 0; j < 10; ++j) o[j] = sb3[j];
    #pragma unroll
    for (int k = 0; k < 16; ++k) {
        float a = h2[k];
        #pragma unroll
        for (int j = 0; j < 10; ++j) o[j] += a * sW3[k * 10 + j];
    }
    #pragma unroll
    for (int j = 0; j < 10; ++j) out[(size_t)node * 10 + j] = o[j];
}

// ---------------- launcher ----------------
extern "C" void kernel_launch(void* const* d_in, const int* in_sizes, int n_in,
                              void* d_out, int out_size)
{
    const float* x     = (const float*)d_in[0];
    const void*  ei    = d_in[1];                 // int64 or int32 (sniffed)
    const float* W_gcn = (const float*)d_in[2];
    const float* b_gcn = (const float*)d_in[3];
    const float* W1    = (const float*)d_in[4];
    const float* b1    = (const float*)d_in[5];
    const float* W2    = (const float*)d_in[6];
    const float* b2    = (const float*)d_in[7];
    const float* W3    = (const float*)d_in[8];
    const float* b3    = (const float*)d_in[9];
    float* out = (float*)d_out;

    detect_kernel<<<1, 32>>>((const int*)ei);
    zero_cnt_kernel<<<(N_NODES + 255) / 256, 256>>>();
    count_kernel<<<(N_EDGES + 255) / 256, 256>>>(ei);
    gemm_kernel<<<(N_NODES + G_TN - 1) / G_TN, 256>>>(x, W_gcn);
    dinv_kernel<<<(N_NODES + 255) / 256, 256>>>();
    init_acc_kernel<<<(N_NODES * 16 + 255) / 256, 256>>>();
    {
        long long total = (long long)N_EDGES * 16;
        int blocks = (int)((total + 255) / 256);
        scatter_kernel<<<blocks, 256>>>(ei);
    }
    mlp_kernel<<<(N_NODES + 127) / 128, 128>>>(b_gcn, W1, b1, W2, b2, W3, b3, out);
}